// round 13
// baseline (speedup 1.0000x reference)
#include <cuda_runtime.h>
#include <cuda_bf16.h>
#include <cstdint>

// LSTM decoder: B=256, T=512, H=1024, O=1
// R12: tcgen05 is unavailable (harness compiles PTX as compute_103; ptxas
// rejects tcgen05 on sm_103). Back to mma.sync. Fix the real R11 bottleneck
// (issue=18%, occ=12% -> latency-bound): 512 threads / 16 warps per CTA,
// warp tile 32x16, same 64x128 CTA tile, same cp.async double buffering.

#define HH   1024
#define BB   256
#define TT   512
#define G4   4096   // 4*H

#define STAGE_ELEMS 27648            // bf16 elems per smem stage
#define STAGE_BYTES (STAGE_ELEMS*2)  // 55296

// -------- device scratch ------------------------------------------------------
__device__ __align__(16) __nv_bfloat16 g_Whi[G4 * HH];     // 8 MB
__device__ __align__(16) __nv_bfloat16 g_Wlo[G4 * HH];     // 8 MB
__device__ __align__(16) float         g_bias[G4];
__device__ __align__(16) float         g_c[BB * HH];       // in-place
__device__ __align__(16) float         g_hT[BB * HH];      // fp32 h for FC
__device__ __align__(16) __nv_bfloat16 g_hhi[2][BB * HH];  // ping-pong h hi
__device__ __align__(16) __nv_bfloat16 g_hlo[2][BB * HH];  // ping-pong h lo

// -------- helpers -------------------------------------------------------------
__device__ __forceinline__ float fsig(float x) {
    return __fdividef(1.0f, 1.0f + __expf(-x));
}
__device__ __forceinline__ float ftanh_acc(float x) {
    return __fdividef(2.0f, 1.0f + __expf(-2.0f * x)) - 1.0f;
}

__device__ __forceinline__ void mma16816(float c[4], const uint32_t a[4], const uint32_t b[2]) {
    asm volatile(
        "mma.sync.aligned.m16n8k16.row.col.f32.bf16.bf16.f32 "
        "{%0,%1,%2,%3}, {%4,%5,%6,%7}, {%8,%9}, {%0,%1,%2,%3};\n"
        : "+f"(c[0]), "+f"(c[1]), "+f"(c[2]), "+f"(c[3])
        : "r"(a[0]), "r"(a[1]), "r"(a[2]), "r"(a[3]), "r"(b[0]), "r"(b[1]));
}

__device__ __forceinline__ void cp16(void* s, const void* g) {
    uint32_t sa = (uint32_t)__cvta_generic_to_shared(s);
    asm volatile("cp.async.cg.shared.global [%0], [%1], 16;\n" :: "r"(sa), "l"(g));
}

// -------- one-time prep -------------------------------------------------------
__global__ void prep_kernel(const float* __restrict__ Whh,
                            const float* __restrict__ bih,
                            const float* __restrict__ bhh,
                            const float* __restrict__ h0,
                            const float* __restrict__ c0) {
    int i = blockIdx.x * blockDim.x + threadIdx.x;
    if (i < G4 * HH) {
        float w = Whh[i];
        __nv_bfloat16 hi = __float2bfloat16(w);
        g_Whi[i] = hi;
        g_Wlo[i] = __float2bfloat16(w - __bfloat162float(hi));
    }
    if (i < BB * HH) {
        float h = h0[i];
        __nv_bfloat16 hb = __float2bfloat16(h);
        g_hhi[0][i] = hb;
        g_hlo[0][i] = __float2bfloat16(h - __bfloat162float(hb));
        g_c[i]  = c0[i];
        g_hT[i] = h;
    }
    if (i < G4) g_bias[i] = bih[i] + bhh[i];
}

// -------- per-timestep kernel -------------------------------------------------
// CTA tile: 64 batch x 32 h-cols (128 gate rows); grid (32,4)=128 CTAs.
// 512 threads = 16 warps in 2(m) x 8(n); warp tile 32(batch) x 16(gates).
// K chunks of 64, double-buffered via cp.async.
// Stage layout (bf16): sAhi[64*72] sAlo[64*72] sBhi[128*72] sBlo[128*72].

__global__ void __launch_bounds__(512, 1)
lstm_step(const float* __restrict__ y_hist, const float* __restrict__ W_ih,
          int t, int src, int dst) {
    extern __shared__ __align__(16) char smem_raw[];
    float* gsm = (float*)smem_raw;                        // epilogue reuse 64*132 f32

    const int tid  = threadIdx.x;
    const int lane = tid & 31;
    const int w    = tid >> 5;
    const int wm   = w & 1;        // 0..1  (m halves of 32)
    const int wn   = w >> 1;       // 0..7  (n tiles of 16)
    const int g    = lane >> 2;    // 0..7
    const int tg   = lane & 3;     // 0..3
    const int bm0  = blockIdx.y * 64;
    const int jh0  = blockIdx.x * 32;

    const __nv_bfloat16* __restrict__ hhi = g_hhi[src];
    const __nv_bfloat16* __restrict__ hlo = g_hlo[src];

    // per-thread load coords
    const int vm  = tid >> 3;        // 0..63  (A row / B row group)
    const int kv  = (tid & 7) * 8;   // elem offset within 64-elem chunk

    float acc[2][2][4];
#pragma unroll
    for (int mt = 0; mt < 2; mt++)
#pragma unroll
        for (int nt = 0; nt < 2; nt++)
#pragma unroll
            for (int q = 0; q < 4; q++) acc[mt][nt][q] = 0.0f;

    // ---- async load of one k-chunk into a stage ----
    auto issue_loads = [&](int stage, int kc0) {
        __nv_bfloat16* sAhi = (__nv_bfloat16*)(smem_raw + stage * STAGE_BYTES);
        __nv_bfloat16* sAlo = sAhi + 64 * 72;
        __nv_bfloat16* sBhi = sAlo + 64 * 72;
        __nv_bfloat16* sBlo = sBhi + 128 * 72;
        {   // A: 512 vectors, one hi + one lo per thread
            int gi = (bm0 + vm) * HH + kc0 + kv;
            cp16(sAhi + vm * 72 + kv, hhi + gi);
            cp16(sAlo + vm * 72 + kv, hlo + gi);
        }
#pragma unroll
        for (int i = 0; i < 2; i++) {   // B: 1024 vectors, 2 hi + 2 lo per thread
            int r = vm + i * 64;
            int grow = ((r >> 5) << 10) + jh0 + (r & 31);  // gate*1024 + jh0 + col
            int gi = grow * HH + kc0 + kv;
            cp16(sBhi + r * 72 + kv, g_Whi + gi);
            cp16(sBlo + r * 72 + kv, g_Wlo + gi);
        }
        asm volatile("cp.async.commit_group;\n");
    };

    issue_loads(0, 0);

    for (int kc = 0; kc < 16; kc++) {
        if (kc + 1 < 16) {
            issue_loads((kc + 1) & 1, (kc + 1) * 64);
            asm volatile("cp.async.wait_group 1;\n");
        } else {
            asm volatile("cp.async.wait_group 0;\n");
        }
        __syncthreads();

        const char* stage = smem_raw + (kc & 1) * STAGE_BYTES;
        const __nv_bfloat16* sAhi = (const __nv_bfloat16*)stage;
        const __nv_bfloat16* sAlo = sAhi + 64 * 72;
        const __nv_bfloat16* sBhi = sAlo + 64 * 72;
        const __nv_bfloat16* sBlo = sBhi + 128 * 72;

#pragma unroll
        for (int ks = 0; ks < 4; ks++) {
            const int kk = ks * 16;
            uint32_t Ahi[2][4], Alo[2][4], Bhi[2][2], Blo[2][2];
            const int abase = (wm * 32 + g) * 72 + kk + 2 * tg;
#pragma unroll
            for (int mt = 0; mt < 2; mt++) {
                int o = abase + mt * 16 * 72;
                Ahi[mt][0] = *(const uint32_t*)(sAhi + o);
                Ahi[mt][1] = *(const uint32_t*)(sAhi + o + 8 * 72);
                Ahi[mt][2] = *(const uint32_t*)(sAhi + o + 8);
                Ahi[mt][3] = *(const uint32_t*)(sAhi + o + 8 * 72 + 8);
                Alo[mt][0] = *(const uint32_t*)(sAlo + o);
                Alo[mt][1] = *(const uint32_t*)(sAlo + o + 8 * 72);
                Alo[mt][2] = *(const uint32_t*)(sAlo + o + 8);
                Alo[mt][3] = *(const uint32_t*)(sAlo + o + 8 * 72 + 8);
            }
            const int bbase = (wn * 16 + g) * 72 + kk + 2 * tg;
#pragma unroll
            for (int nt = 0; nt < 2; nt++) {
                int o = bbase + nt * 8 * 72;
                Bhi[nt][0] = *(const uint32_t*)(sBhi + o);
                Bhi[nt][1] = *(const uint32_t*)(sBhi + o + 8);
                Blo[nt][0] = *(const uint32_t*)(sBlo + o);
                Blo[nt][1] = *(const uint32_t*)(sBlo + o + 8);
            }
            // emulated fp32: hi*hi + hi*lo + lo*hi
#pragma unroll
            for (int mt = 0; mt < 2; mt++)
#pragma unroll
                for (int nt = 0; nt < 2; nt++) mma16816(acc[mt][nt], Ahi[mt], Bhi[nt]);
#pragma unroll
            for (int mt = 0; mt < 2; mt++)
#pragma unroll
                for (int nt = 0; nt < 2; nt++) mma16816(acc[mt][nt], Ahi[mt], Blo[nt]);
#pragma unroll
            for (int mt = 0; mt < 2; mt++)
#pragma unroll
                for (int nt = 0; nt < 2; nt++) mma16816(acc[mt][nt], Alo[mt], Bhi[nt]);
        }
        __syncthreads();
    }

    // ---- gates -> smem for cross-thread recombination ----
#pragma unroll
    for (int mt = 0; mt < 2; mt++)
#pragma unroll
        for (int nt = 0; nt < 2; nt++) {
            int rr = wm * 32 + mt * 16 + g;     // batch row in tile
            int cc = wn * 16 + nt * 8 + 2 * tg; // gate col (0..127)
            gsm[rr * 132 + cc]           = acc[mt][nt][0];
            gsm[rr * 132 + cc + 1]       = acc[mt][nt][1];
            gsm[(rr + 8) * 132 + cc]     = acc[mt][nt][2];
            gsm[(rr + 8) * 132 + cc + 1] = acc[mt][nt][3];
        }
    __syncthreads();

    // ---- activations: thread -> column jl, 4 batch rows ----
    const int jl = tid & 31;
    const int rb = (tid >> 5) * 4;
    const int jg = jh0 + jl;
    const float bi  = g_bias[jg],          wi = W_ih[jg];
    const float bff = g_bias[HH + jg],     wf = W_ih[HH + jg];
    const float bg  = g_bias[2 * HH + jg], wg = W_ih[2 * HH + jg];
    const float bo  = g_bias[3 * HH + jg], wo = W_ih[3 * HH + jg];
    __nv_bfloat16* __restrict__ dhhi = g_hhi[dst];
    __nv_bfloat16* __restrict__ dhlo = g_hlo[dst];

#pragma unroll
    for (int i = 0; i < 4; i++) {
        int r = rb + i;
        int b = bm0 + r;
        float x = y_hist[b * TT + t];
        float gi_ = gsm[r * 132 + jl]      + x * wi + bi;
        float gf_ = gsm[r * 132 + 32 + jl] + x * wf + bff;
        float gg_ = gsm[r * 132 + 64 + jl] + x * wg + bg;
        float go_ = gsm[r * 132 + 96 + jl] + x * wo + bo;
        float si = fsig(gi_), sf = fsig(gf_), so = fsig(go_);
        float tgg = ftanh_acc(gg_);
        int idx = b * HH + jg;
        float cn = sf * g_c[idx] + si * tgg;
        g_c[idx] = cn;
        float hv = so * ftanh_acc(cn);
        g_hT[idx] = hv;
        __nv_bfloat16 hb = __float2bfloat16(hv);
        dhhi[idx] = hb;
        dhlo[idx] = __float2bfloat16(hv - __bfloat162float(hb));
    }
}

// -------- final FC ------------------------------------------------------------
__global__ void fc_kernel(const float* __restrict__ Wfc, const float* __restrict__ bfc,
                          float* __restrict__ out) {
    int b = blockIdx.x;
    float s = 0.0f;
    for (int j = threadIdx.x; j < HH; j += 256) s += g_hT[b * HH + j] * Wfc[j];
#pragma unroll
    for (int o = 16; o > 0; o >>= 1) s += __shfl_xor_sync(0xffffffffu, s, o);
    __shared__ float red[8];
    if ((threadIdx.x & 31) == 0) red[threadIdx.x >> 5] = s;
    __syncthreads();
    if (threadIdx.x == 0) {
        float tot = 0.0f;
#pragma unroll
        for (int i = 0; i < 8; i++) tot += red[i];
        out[b] = tot + bfc[0];
    }
}

// -------- launch --------------------------------------------------------------
extern "C" void kernel_launch(void* const* d_in, const int* in_sizes, int n_in,
                              void* d_out, int out_size) {
    (void)in_sizes; (void)n_in; (void)out_size;
    const float* y_hist = (const float*)d_in[0];
    const float* W_ih   = (const float*)d_in[1];
    const float* W_hh   = (const float*)d_in[2];
    const float* b_ih   = (const float*)d_in[3];
    const float* b_hh   = (const float*)d_in[4];
    const float* W_fc   = (const float*)d_in[5];
    const float* b_fc   = (const float*)d_in[6];
    const float* h0     = (const float*)d_in[7];
    const float* c0     = (const float*)d_in[8];
    float* out = (float*)d_out;

    cudaFuncSetAttribute(lstm_step, cudaFuncAttributeMaxDynamicSharedMemorySize,
                         2 * STAGE_BYTES);

    prep_kernel<<<(G4 * HH + 255) / 256, 256>>>(W_hh, b_ih, b_hh, h0, c0);

    dim3 grid(32, 4);  // 128 CTAs, single wave
    for (int t = 0; t < TT; t++) {
        lstm_step<<<grid, 512, 2 * STAGE_BYTES>>>(y_hist, W_ih, t, t & 1, (t & 1) ^ 1);
    }
    fc_kernel<<<256, 256>>>(W_fc, b_fc, out);
}

// round 14
// speedup vs baseline: 1.0893x; 1.0893x over previous
#include <cuda_runtime.h>
#include <cuda_bf16.h>
#include <cstdint>

// LSTM decoder: B=256, T=512, H=1024, O=1
// R14: fix the smem-load wall found in R13.
//  - ldmatrix.x4 fragment loads (conflict-free w/ 72-elem row padding)
//  - 16 warps as 2(m) x 4(n) x 2(split-K); split-K partials summed in epilogue
//  - cp.async double-buffered stages, 3-pass bf16 hi/lo emulation (unchanged)

#define HH   1024
#define BB   256
#define TT   512
#define G4   4096

#define OFF_AHI 0
#define OFF_ALO 9216
#define OFF_BHI 18432
#define OFF_BLO 36864
#define STAGE_BYTES 55296

// -------- device scratch ------------------------------------------------------
__device__ __align__(16) __nv_bfloat16 g_Whi[G4 * HH];
__device__ __align__(16) __nv_bfloat16 g_Wlo[G4 * HH];
__device__ __align__(16) float         g_bias[G4];
__device__ __align__(16) float         g_c[BB * HH];
__device__ __align__(16) float         g_hT[BB * HH];
__device__ __align__(16) __nv_bfloat16 g_hhi[2][BB * HH];
__device__ __align__(16) __nv_bfloat16 g_hlo[2][BB * HH];

// -------- helpers -------------------------------------------------------------
__device__ __forceinline__ float fsig(float x) {
    return __fdividef(1.0f, 1.0f + __expf(-x));
}
__device__ __forceinline__ float ftanh_acc(float x) {
    return __fdividef(2.0f, 1.0f + __expf(-2.0f * x)) - 1.0f;
}

__device__ __forceinline__ void mma16816(float c[4], const uint32_t a[4],
                                         uint32_t b0, uint32_t b1) {
    asm volatile(
        "mma.sync.aligned.m16n8k16.row.col.f32.bf16.bf16.f32 "
        "{%0,%1,%2,%3}, {%4,%5,%6,%7}, {%8,%9}, {%0,%1,%2,%3};\n"
        : "+f"(c[0]), "+f"(c[1]), "+f"(c[2]), "+f"(c[3])
        : "r"(a[0]), "r"(a[1]), "r"(a[2]), "r"(a[3]), "r"(b0), "r"(b1));
}

__device__ __forceinline__ void ldsm4(uint32_t r[4], uint32_t saddr) {
    asm volatile("ldmatrix.sync.aligned.m8n8.x4.shared.b16 {%0,%1,%2,%3}, [%4];"
        : "=r"(r[0]), "=r"(r[1]), "=r"(r[2]), "=r"(r[3]) : "r"(saddr));
}

__device__ __forceinline__ void cp16(void* s, const void* g) {
    uint32_t sa = (uint32_t)__cvta_generic_to_shared(s);
    asm volatile("cp.async.cg.shared.global [%0], [%1], 16;\n" :: "r"(sa), "l"(g));
}

// -------- one-time prep -------------------------------------------------------
__global__ void prep_kernel(const float* __restrict__ Whh,
                            const float* __restrict__ bih,
                            const float* __restrict__ bhh,
                            const float* __restrict__ h0,
                            const float* __restrict__ c0) {
    int i = blockIdx.x * blockDim.x + threadIdx.x;
    if (i < G4 * HH) {
        float w = Whh[i];
        __nv_bfloat16 hi = __float2bfloat16(w);
        g_Whi[i] = hi;
        g_Wlo[i] = __float2bfloat16(w - __bfloat162float(hi));
    }
    if (i < BB * HH) {
        float h = h0[i];
        __nv_bfloat16 hb = __float2bfloat16(h);
        g_hhi[0][i] = hb;
        g_hlo[0][i] = __float2bfloat16(h - __bfloat162float(hb));
        g_c[i]  = c0[i];
        g_hT[i] = h;
    }
    if (i < G4) g_bias[i] = bih[i] + bhh[i];
}

// -------- per-timestep kernel -------------------------------------------------
// CTA tile: 64 batch x 32 h-cols (128 gate rows); grid (32,4)=128 CTAs.
// 512 threads / 16 warps: wk = w&1 (k-half), wm = (w>>1)&1 (batch 32-half),
// wn = w>>2 (gate 32-group). Warp tile 32x32 over its 32-wide k-half.
// K chunks of 64, double-buffered cp.async. Fragments via ldmatrix.x4.

__global__ void __launch_bounds__(512, 1)
lstm_step(const float* __restrict__ y_hist, const float* __restrict__ W_ih,
          int t, int src, int dst) {
    extern __shared__ __align__(16) char smem_raw[];

    const int tid  = threadIdx.x;
    const int lane = tid & 31;
    const int w    = tid >> 5;
    const int wk   = w & 1;
    const int wm   = (w >> 1) & 1;
    const int wn   = w >> 2;
    const int g    = lane >> 2;
    const int tg   = lane & 3;
    const int bm0  = blockIdx.y * 64;
    const int jh0  = blockIdx.x * 32;

    const __nv_bfloat16* __restrict__ hhi = g_hhi[src];
    const __nv_bfloat16* __restrict__ hlo = g_hlo[src];

    const uint32_t smem_u32 = (uint32_t)__cvta_generic_to_shared(smem_raw);

    // per-lane ldmatrix address components (byte offsets within a region)
    const int a_row = lane & 15;               // row within 16-row tile
    const int a_kb  = (lane >> 4) * 16;        // +8 elems for upper half
    const int b_row = (lane & 7) + ((lane >> 4) << 3);
    const int b_kb  = ((lane >> 3) & 1) * 16;

    // row-part offsets (bytes), add k-chunk byte offset per ks
    int aoffm[2], boffn[2];
#pragma unroll
    for (int mt = 0; mt < 2; mt++)
        aoffm[mt] = (wm * 32 + mt * 16 + a_row) * 144 + a_kb;
#pragma unroll
    for (int nb = 0; nb < 2; nb++)
        boffn[nb] = (wn * 32 + nb * 16 + b_row) * 144 + b_kb;

    // per-thread cp.async coords
    const int vm = tid >> 3;            // 0..63
    const int kv = (tid & 7) * 8;       // elem offset in 64-chunk

    float acc[2][4][4];
#pragma unroll
    for (int mt = 0; mt < 2; mt++)
#pragma unroll
        for (int nt = 0; nt < 4; nt++)
#pragma unroll
            for (int q = 0; q < 4; q++) acc[mt][nt][q] = 0.0f;

    auto issue_loads = [&](int stage, int kc0) {
        char* stg = smem_raw + stage * STAGE_BYTES;
        __nv_bfloat16* sAhi = (__nv_bfloat16*)(stg + OFF_AHI);
        __nv_bfloat16* sAlo = (__nv_bfloat16*)(stg + OFF_ALO);
        __nv_bfloat16* sBhi = (__nv_bfloat16*)(stg + OFF_BHI);
        __nv_bfloat16* sBlo = (__nv_bfloat16*)(stg + OFF_BLO);
        {   // A (h): 64 rows x 8 vec, 512 vectors, 1 hi + 1 lo per thread
            int gi = (bm0 + vm) * HH + kc0 + kv;
            cp16(sAhi + vm * 72 + kv, hhi + gi);
            cp16(sAlo + vm * 72 + kv, hlo + gi);
        }
#pragma unroll
        for (int i = 0; i < 2; i++) {   // B (W): 128 rows, 2 hi + 2 lo per thread
            int r = vm + i * 64;
            int grow = ((r >> 5) << 10) + jh0 + (r & 31);
            int gi = grow * HH + kc0 + kv;
            cp16(sBhi + r * 72 + kv, g_Whi + gi);
            cp16(sBlo + r * 72 + kv, g_Wlo + gi);
        }
        asm volatile("cp.async.commit_group;\n");
    };

    issue_loads(0, 0);

    for (int kc = 0; kc < 16; kc++) {
        if (kc + 1 < 16) {
            issue_loads((kc + 1) & 1, (kc + 1) * 64);
            asm volatile("cp.async.wait_group 1;\n");
        } else {
            asm volatile("cp.async.wait_group 0;\n");
        }
        __syncthreads();

        const uint32_t stg = smem_u32 + (kc & 1) * STAGE_BYTES;

#pragma unroll
        for (int ks = 0; ks < 2; ks++) {
            const int kb = (wk * 32 + ks * 16) * 2;   // k byte offset in row
            uint32_t Ahi[2][4], Alo[2][4], Bhi[2][4], Blo[2][4];
#pragma unroll
            for (int mt = 0; mt < 2; mt++) {
                ldsm4(Ahi[mt], stg + OFF_AHI + aoffm[mt] + kb);
                ldsm4(Alo[mt], stg + OFF_ALO + aoffm[mt] + kb);
            }
#pragma unroll
            for (int nb = 0; nb < 2; nb++) {
                ldsm4(Bhi[nb], stg + OFF_BHI + boffn[nb] + kb);
                ldsm4(Blo[nb], stg + OFF_BLO + boffn[nb] + kb);
            }
            // pass 1: Ahi*Bhi
#pragma unroll
            for (int mt = 0; mt < 2; mt++)
#pragma unroll
                for (int nt = 0; nt < 4; nt++)
                    mma16816(acc[mt][nt], Ahi[mt], Bhi[nt >> 1][(nt & 1) * 2],
                             Bhi[nt >> 1][(nt & 1) * 2 + 1]);
            // pass 2: Ahi*Blo
#pragma unroll
            for (int mt = 0; mt < 2; mt++)
#pragma unroll
                for (int nt = 0; nt < 4; nt++)
                    mma16816(acc[mt][nt], Ahi[mt], Blo[nt >> 1][(nt & 1) * 2],
                             Blo[nt >> 1][(nt & 1) * 2 + 1]);
            // pass 3: Alo*Bhi
#pragma unroll
            for (int mt = 0; mt < 2; mt++)
#pragma unroll
                for (int nt = 0; nt < 4; nt++)
                    mma16816(acc[mt][nt], Alo[mt], Bhi[nt >> 1][(nt & 1) * 2],
                             Bhi[nt >> 1][(nt & 1) * 2 + 1]);
        }
        __syncthreads();
    }

    // ---- split-K partials -> two smem planes ----
    float* gsm = (float*)smem_raw + wk * (64 * 132);
#pragma unroll
    for (int mt = 0; mt < 2; mt++)
#pragma unroll
        for (int nt = 0; nt < 4; nt++) {
            int rr = wm * 32 + mt * 16 + g;
            int cc = wn * 32 + nt * 8 + 2 * tg;
            gsm[rr * 132 + cc]           = acc[mt][nt][0];
            gsm[rr * 132 + cc + 1]       = acc[mt][nt][1];
            gsm[(rr + 8) * 132 + cc]     = acc[mt][nt][2];
            gsm[(rr + 8) * 132 + cc + 1] = acc[mt][nt][3];
        }
    __syncthreads();

    // ---- activations: thread -> column jl, 4 batch rows; sum the 2 k-planes --
    const float* gsm0 = (const float*)smem_raw;
    const float* gsm1 = gsm0 + 64 * 132;
    const int jl = tid & 31;
    const int rb = (tid >> 5) * 4;
    const int jg = jh0 + jl;
    const float bi  = g_bias[jg],          wi = W_ih[jg];
    const float bff = g_bias[HH + jg],     wf = W_ih[HH + jg];
    const float bg  = g_bias[2 * HH + jg], wg = W_ih[2 * HH + jg];
    const float bo  = g_bias[3 * HH + jg], wo = W_ih[3 * HH + jg];
    __nv_bfloat16* __restrict__ dhhi = g_hhi[dst];
    __nv_bfloat16* __restrict__ dhlo = g_hlo[dst];

#pragma unroll
    for (int i = 0; i < 4; i++) {
        int r = rb + i;
        int b = bm0 + r;
        float x = y_hist[b * TT + t];
        float gi_ = gsm0[r * 132 + jl]      + gsm1[r * 132 + jl]      + x * wi + bi;
        float gf_ = gsm0[r * 132 + 32 + jl] + gsm1[r * 132 + 32 + jl] + x * wf + bff;
        float gg_ = gsm0[r * 132 + 64 + jl] + gsm1[r * 132 + 64 + jl] + x * wg + bg;
        float go_ = gsm0[r * 132 + 96 + jl] + gsm1[r * 132 + 96 + jl] + x * wo + bo;
        float si = fsig(gi_), sf = fsig(gf_), so = fsig(go_);
        float tgg = ftanh_acc(gg_);
        int idx = b * HH + jg;
        float cn = sf * g_c[idx] + si * tgg;
        g_c[idx] = cn;
        float hv = so * ftanh_acc(cn);
        g_hT[idx] = hv;
        __nv_bfloat16 hb = __float2bfloat16(hv);
        dhhi[idx] = hb;
        dhlo[idx] = __float2bfloat16(hv - __bfloat162float(hb));
    }
}

// -------- final FC ------------------------------------------------------------
__global__ void fc_kernel(const float* __restrict__ Wfc, const float* __restrict__ bfc,
                          float* __restrict__ out) {
    int b = blockIdx.x;
    float s = 0.0f;
    for (int j = threadIdx.x; j < HH; j += 256) s += g_hT[b * HH + j] * Wfc[j];
#pragma unroll
    for (int o = 16; o > 0; o >>= 1) s += __shfl_xor_sync(0xffffffffu, s, o);
    __shared__ float red[8];
    if ((threadIdx.x & 31) == 0) red[threadIdx.x >> 5] = s;
    __syncthreads();
    if (threadIdx.x == 0) {
        float tot = 0.0f;
#pragma unroll
        for (int i = 0; i < 8; i++) tot += red[i];
        out[b] = tot + bfc[0];
    }
}

// -------- launch --------------------------------------------------------------
extern "C" void kernel_launch(void* const* d_in, const int* in_sizes, int n_in,
                              void* d_out, int out_size) {
    (void)in_sizes; (void)n_in; (void)out_size;
    const float* y_hist = (const float*)d_in[0];
    const float* W_ih   = (const float*)d_in[1];
    const float* W_hh   = (const float*)d_in[2];
    const float* b_ih   = (const float*)d_in[3];
    const float* b_hh   = (const float*)d_in[4];
    const float* W_fc   = (const float*)d_in[5];
    const float* b_fc   = (const float*)d_in[6];
    const float* h0     = (const float*)d_in[7];
    const float* c0     = (const float*)d_in[8];
    float* out = (float*)d_out;

    cudaFuncSetAttribute(lstm_step, cudaFuncAttributeMaxDynamicSharedMemorySize,
                         2 * STAGE_BYTES);

    prep_kernel<<<(G4 * HH + 255) / 256, 256>>>(W_hh, b_ih, b_hh, h0, c0);

    dim3 grid(32, 4);  // 128 CTAs, single wave
    for (int t = 0; t < TT; t++) {
        lstm_step<<<grid, 512, 2 * STAGE_BYTES>>>(y_hist, W_ih, t, t & 1, (t & 1) ^ 1);
    }
    fc_kernel<<<256, 256>>>(W_fc, b_fc, out);
}